// round 17
// baseline (speedup 1.0000x reference)
#include <cuda_runtime.h>
#include <cuda_fp16.h>
#include <cstdint>
#include <math.h>

#define BB 8192
#define DD 1024
#define EE 8
#define NQv 8
#define NLv 2
#define HHv 1024

// ---------------- scratch (static device globals: no allocation) ----------------
__device__ float g_X1[(size_t)BB * DD];                 // inter-block activations
__device__ __half g_Hf[(size_t)BB * 2 * HHv];           // hidden, fp16
__device__ __half g_Eout[(size_t)BB * 2 * DD];          // per-slot GEMM output (fp16)
__device__ __half g_w2T[(size_t)2 * EE * DD * HHv];     // w2^T [e][n][k] fp16
__device__ float g_gWT[(size_t)2 * EE * DD];            // gate W transposed [blk][e][d]
__device__ float g_qv[(size_t)BB * 2 * NQv];            // per-slot Z expectations
__device__ int   g_cnt[EE];
__device__ int   g_list[EE * BB];                       // entries encode row*2+slot
__device__ int2   g_sel[BB];                            // per-row selected experts
__device__ float2 g_wgt[BB];                            // per-row gate weights

// ---------------- generic PTX helpers ----------------
static __device__ __forceinline__ uint32_t smem_u32(const void* p) {
    uint32_t a;
    asm("{ .reg .u64 t; cvta.to.shared.u64 t, %1; cvt.u32.u64 %0, t; }" : "=r"(a) : "l"(p));
    return a;
}
static __device__ __forceinline__ void cp16(uint32_t dst, const void* src) {
    asm volatile("cp.async.cg.shared.global [%0], [%1], 16;" :: "r"(dst), "l"(src) : "memory");
}
static __device__ __forceinline__ void cp16z(uint32_t dst, const void* src, int srcsize) {
    asm volatile("cp.async.cg.shared.global [%0], [%1], 16, %2;" :: "r"(dst), "l"(src), "r"(srcsize) : "memory");
}
static __device__ __forceinline__ void cp_commit() {
    asm volatile("cp.async.commit_group;" ::: "memory");
}
static __device__ __forceinline__ void ldm4(uint32_t* r, uint32_t addr) {
    asm volatile("ldmatrix.sync.aligned.m8n8.x4.shared.b16 {%0,%1,%2,%3}, [%4];"
        : "=r"(r[0]), "=r"(r[1]), "=r"(r[2]), "=r"(r[3]) : "r"(addr));
}
static __device__ __forceinline__ void mma16816(float* c, const uint32_t* a, const uint32_t* b) {
    asm volatile("mma.sync.aligned.m16n8k16.row.col.f32.f16.f16.f32 "
        "{%0,%1,%2,%3}, {%4,%5,%6,%7}, {%8,%9}, {%0,%1,%2,%3};"
        : "+f"(c[0]), "+f"(c[1]), "+f"(c[2]), "+f"(c[3])
        : "r"(a[0]), "r"(a[1]), "r"(a[2]), "r"(a[3]), "r"(b[0]), "r"(b[1]));
}

// ---------------- GEMM tile config (fp16 single-pass; BK=64, 3-stage ring) ----------------
#define BM 128
#define BN 128
#define BK 64
#define NCH (HHv / BK)                 // 16
#define RSTR 144                        // bytes per SMEM row (128 data + 16 pad; conflict-free)
#define TILE_BYT (BM * RSTR)            // 18432
#define STAGE_BYT (2 * TILE_BYT)        // 36864: A, B
#define NSTAGE 3
#define GEMM_SMEM (NSTAGE * STAGE_BYT)  // 110592

// ---------------- gate W transpose ----------------
__global__ __launch_bounds__(256) void k_gwt(const float* __restrict__ gW)
{
    int i = blockIdx.x * 256 + threadIdx.x;
    if (i < 2 * DD * EE) {
        int blk = i / (DD * EE);
        int r = i % (DD * EE);
        int d = r / EE, e = r % EE;
        g_gWT[(size_t)blk * EE * DD + (size_t)e * DD + d] = gW[i];
    }
}

// ---------------- w2 -> w2^T fp16 (+ reset cnt) ----------------
__global__ __launch_bounds__(256) void k_w2t(const float* __restrict__ w2)
{
    __shared__ float tile[32][33];
    int ez = blockIdx.z;
    int k0 = blockIdx.y * 32;
    int n0 = blockIdx.x * 32;
    int tx = threadIdx.x & 31, ty = threadIdx.x >> 5;

    if (blockIdx.x == 0 && blockIdx.y == 0 && blockIdx.z == 0 && threadIdx.x < EE)
        g_cnt[threadIdx.x] = 0;

    const float* src = w2 + (size_t)ez * HHv * DD;
    #pragma unroll
    for (int r = 0; r < 32; r += 8)
        tile[ty + r][tx] = src[(size_t)(k0 + ty + r) * DD + n0 + tx];
    __syncthreads();

    __half* dst = g_w2T + (size_t)ez * DD * HHv;
    #pragma unroll
    for (int r = 0; r < 32; r += 8) {
        float v = tile[tx][ty + r];
        dst[(size_t)(n0 + ty + r) * HHv + k0 + tx] = __float2half(v);
    }
}

// ---------------- warp-resident gate + qsim (1 warp per row; q vectors out) ----------------
__global__ __launch_bounds__(256) void k_gate_qsim_w(
    const float* __restrict__ Xext,
    const float* __restrict__ gb,
    const float* __restrict__ qp,
    int blk)
{
    __shared__ float2 stbuf[8][256];     // per-warp CNOT permute buffer
    const unsigned FULL = 0xffffffffu;
    int wid = threadIdx.x >> 5;
    int lane = threadIdx.x & 31;
    int b = blockIdx.x * 8 + wid;

    const float* X = (blk == 0) ? Xext : g_X1;
    const float4* xr4 = (const float4*)(X + (size_t)b * DD);

    float4 xv[8];
    #pragma unroll
    for (int j = 0; j < 8; j++) xv[j] = xr4[j * 32 + lane];

    // ---- gate logits (transposed gW: fully coalesced) ----
    float acc[EE];
    const float4* gT4 = (const float4*)(g_gWT + (size_t)blk * EE * DD);
    #pragma unroll
    for (int e = 0; e < EE; e++) {
        const float4* ge = gT4 + (size_t)e * (DD / 4);
        float a = 0.f;
        #pragma unroll
        for (int j = 0; j < 8; j++) {
            float4 g = ge[j * 32 + lane];
            a += xv[j].x * g.x + xv[j].y * g.y + xv[j].z * g.z + xv[j].w * g.w;
        }
        acc[e] = a;
    }
    #pragma unroll
    for (int e = 0; e < EE; e++) {
        #pragma unroll
        for (int o = 16; o > 0; o >>= 1) acc[e] += __shfl_xor_sync(FULL, acc[e], o);
    }

    // ---- softmax + top2 (redundant on all lanes) ----
    float l[EE], mx = -1e30f;
    #pragma unroll
    for (int e = 0; e < EE; e++) { l[e] = acc[e] + gb[blk * EE + e]; mx = fmaxf(mx, l[e]); }
    float sum = 0.f;
    #pragma unroll
    for (int e = 0; e < EE; e++) { l[e] = expf(l[e] - mx); sum += l[e]; }
    float inv = 1.f / sum;
    #pragma unroll
    for (int e = 0; e < EE; e++) l[e] *= inv;
    int i0 = 0;
    #pragma unroll
    for (int e = 1; e < EE; e++) if (l[e] > l[i0]) i0 = e;
    int i1 = (i0 == 0) ? 1 : 0;
    #pragma unroll
    for (int e = 0; e < EE; e++) if (e != i1 && e != i0 && l[e] > l[i1]) i1 = e;
    float p0 = l[i0], p1 = l[i1];
    float w1 = 1.f / (1.f + expf(p0 - p1));
    float w0 = 1.f - w1;
    if (lane == 0) {
        int pos0 = atomicAdd(&g_cnt[i0], 1); g_list[i0 * BB + pos0] = b * 2 + 0;
        int pos1 = atomicAdd(&g_cnt[i1], 1); g_list[i1 * BB + pos1] = b * 2 + 1;
        g_sel[b] = make_int2(i0, i1);
        g_wgt[b] = make_float2(w0, w1);
    }

    // ---- per-qubit angle cos/sin ----
    float v0 = __shfl_sync(FULL, xv[0].x, lane >> 2);
    float v1 = __shfl_sync(FULL, xv[0].y, lane >> 2);
    float v2 = __shfl_sync(FULL, xv[0].z, lane >> 2);
    float v3 = __shfl_sync(FULL, xv[0].w, lane >> 2);
    float xq = (lane & 2) ? ((lane & 1) ? v3 : v2) : ((lane & 1) ? v1 : v0);
    float cq_own, sq_own;
    sincosf(0.5f * xq, &sq_own, &cq_own);
    float cqv[NQv], sqv[NQv];
    #pragma unroll
    for (int q = 0; q < NQv; q++) {
        cqv[q] = __shfl_sync(FULL, cq_own, q);
        sqv[q] = __shfl_sync(FULL, sq_own, q);
    }

    int esel[2] = { i0, i1 };
    float2* sw = stbuf[wid];

    #pragma unroll
    for (int s = 0; s < 2; s++) {
        int e = esel[s];

        float2 st[8];
        #pragma unroll
        for (int j = 0; j < 8; j++) {
            int idx = lane * 8 + j;
            float v = 1.f;
            #pragma unroll
            for (int q = 0; q < NQv; q++)
                v *= ((idx >> (NQv - 1 - q)) & 1) ? sqv[q] : cqv[q];
            st[j] = make_float2(v, 0.f);
        }

        const float* qpe = qp + (size_t)(blk * EE + e) * NLv * NQv * 3;
        #pragma unroll
        for (int lyr = 0; lyr < NLv; lyr++) {
            const float* pp = qpe + (lyr * NQv + (lane & 7)) * 3;
            float phi = pp[0], th = pp[1], om = pp[2];
            float c, sn; sincosf(0.5f * th, &sn, &c);
            float sa, ca; sincosf(0.5f * (phi + om), &sa, &ca);
            float sb, cb; sincosf(0.5f * (phi - om), &sb, &cb);
            float o00r = ca * c,  o00i = -sa * c;
            float o11r = ca * c,  o11i =  sa * c;
            float o01r = -cb * sn, o01i = -sb * sn;
            float o10r =  cb * sn, o10i = -sb * sn;

            #pragma unroll
            for (int q = 0; q < NQv; q++) {
                float M00r = __shfl_sync(FULL, o00r, q), M00i = __shfl_sync(FULL, o00i, q);
                float M01r = __shfl_sync(FULL, o01r, q), M01i = __shfl_sync(FULL, o01i, q);
                float M10r = __shfl_sync(FULL, o10r, q), M10i = __shfl_sync(FULL, o10i, q);
                float M11r = __shfl_sync(FULL, o11r, q), M11i = __shfl_sync(FULL, o11i, q);
                const int pb = NQv - 1 - q;
                if (pb >= 3) {
                    int msk = 1 << (pb - 3);
                    int bit = (lane >> (pb - 3)) & 1;
                    float Msr = bit ? M11r : M00r, Msi = bit ? M11i : M00i;
                    float Mpr = bit ? M10r : M01r, Mpi = bit ? M10i : M01i;
                    #pragma unroll
                    for (int j = 0; j < 8; j++) {
                        float px = __shfl_xor_sync(FULL, st[j].x, msk);
                        float py = __shfl_xor_sync(FULL, st[j].y, msk);
                        float nx = Msr * st[j].x - Msi * st[j].y + Mpr * px - Mpi * py;
                        float ny = Msr * st[j].y + Msi * st[j].x + Mpr * py + Mpi * px;
                        st[j] = make_float2(nx, ny);
                    }
                } else {
                    const int m = 1 << pb;
                    #pragma unroll
                    for (int j = 0; j < 8; j++) {
                        if (!(j & m)) {
                            float2 a0 = st[j], a1 = st[j | m];
                            float2 n0, n1;
                            n0.x = M00r * a0.x - M00i * a0.y + M01r * a1.x - M01i * a1.y;
                            n0.y = M00r * a0.y + M00i * a0.x + M01r * a1.y + M01i * a1.x;
                            n1.x = M10r * a0.x - M10i * a0.y + M11r * a1.x - M11i * a1.y;
                            n1.y = M10r * a0.y + M10i * a0.x + M11r * a1.y + M11i * a1.x;
                            st[j] = n0; st[j | m] = n1;
                        }
                    }
                }
            }
            #pragma unroll
            for (int j = 0; j < 8; j++) sw[lane * 8 + j] = st[j];
            __syncwarp();
            #pragma unroll
            for (int j = 0; j < 8; j++) {
                int idx = lane * 8 + j;
                int jsrc = idx;
                #pragma unroll
                for (int q = NQv - 2; q >= 0; q--) {
                    int pc = NQv - 1 - q, pt = NQv - 2 - q;
                    jsrc ^= ((jsrc >> pc) & 1) << pt;
                }
                st[j] = sw[jsrc];
            }
            __syncwarp();
        }

        // ---- Z expectations -> g_qv ----
        float zp[NQv];
        #pragma unroll
        for (int k = 0; k < NQv; k++) zp[k] = 0.f;
        #pragma unroll
        for (int j = 0; j < 8; j++) {
            int idx = lane * 8 + j;
            float p = st[j].x * st[j].x + st[j].y * st[j].y;
            #pragma unroll
            for (int k = 0; k < NQv; k++)
                zp[k] += ((idx >> (NQv - 1 - k)) & 1) ? -p : p;
        }
        #pragma unroll
        for (int k = 0; k < NQv; k++) {
            #pragma unroll
            for (int o = 16; o > 0; o >>= 1) zp[k] += __shfl_xor_sync(FULL, zp[k], o);
        }
        if (lane == 0) {
            size_t slot = (size_t)b * 2 + s;
            *(float4*)(g_qv + slot * NQv)     = make_float4(zp[0], zp[1], zp[2], zp[3]);
            *(float4*)(g_qv + slot * NQv + 4) = make_float4(zp[4], zp[5], zp[6], zp[7]);
        }
    }
}

// ---------------- grouped hidden layer: rW in REGISTERS, no SMEM ----------------
#define HSLOTS 128
__global__ __launch_bounds__(256) void k_hidden(
    const float* __restrict__ rW, const float* __restrict__ rb, int blk)
{
    int e = blockIdx.x;
    int tile = blockIdx.y;
    int n_e = g_cnt[e];
    int idx0 = tile * HSLOTS;
    if (idx0 >= n_e) return;

    int t = threadIdx.x;   // each thread owns output columns 4t..4t+3

    // rW slice in registers: 8 qubits x 4 columns = 32 regs
    const float4* rW4 = (const float4*)(rW + (size_t)(blk * EE + e) * NQv * HHv);
    float4 w[NQv];
    #pragma unroll
    for (int jj = 0; jj < NQv; jj++) w[jj] = __ldg(rW4 + jj * 256 + t);
    float4 rbv = __ldg((const float4*)(rb + (size_t)(blk * EE + e) * HHv) + t);

    int cnt = min(n_e, idx0 + HSLOTS) - idx0;
    const int* lst = g_list + e * BB + idx0;

    // prefetch slot 0
    int entry = __ldg(lst);
    float2 wp = g_wgt[entry >> 1];
    float wgt = (entry & 1) ? wp.y : wp.x;
    const float4* qv4 = (const float4*)(g_qv + (size_t)entry * NQv);
    float4 q0 = __ldg(qv4), q1 = __ldg(qv4 + 1);

    for (int i = 0; i < cnt; i++) {
        int entry_n = 0; float wgt_n = 0.f; float4 q0n = q0, q1n = q1;
        if (i + 1 < cnt) {
            entry_n = __ldg(lst + i + 1);
            float2 wpn = g_wgt[entry_n >> 1];
            wgt_n = (entry_n & 1) ? wpn.y : wpn.x;
            const float4* qn = (const float4*)(g_qv + (size_t)entry_n * NQv);
            q0n = __ldg(qn); q1n = __ldg(qn + 1);
        }

        float qr[NQv] = { q0.x, q0.y, q0.z, q0.w, q1.x, q1.y, q1.z, q1.w };
        float4 a = rbv;
        #pragma unroll
        for (int jj = 0; jj < NQv; jj++) {
            a.x += qr[jj] * w[jj].x; a.y += qr[jj] * w[jj].y;
            a.z += qr[jj] * w[jj].z; a.w += qr[jj] * w[jj].w;
        }
        a.x = fmaxf(a.x, 0.f) * wgt; a.y = fmaxf(a.y, 0.f) * wgt;
        a.z = fmaxf(a.z, 0.f) * wgt; a.w = fmaxf(a.w, 0.f) * wgt;

        __half2 h0 = __floats2half2_rn(a.x, a.y);
        __half2 h1 = __floats2half2_rn(a.z, a.w);
        uint2 uh;
        uh.x = *(uint32_t*)&h0;
        uh.y = *(uint32_t*)&h1;
        ((uint2*)(g_Hf + (size_t)entry * HHv))[t] = uh;

        entry = entry_n; wgt = wgt_n; q0 = q0n; q1 = q1n;
    }
}

// ---------------- grouped expert GEMM via mma.sync (fp16, BK=64, 3-stage) ----------------
__global__ __launch_bounds__(256, 2) void k_moe_gemm_mma(int blk)
{
    extern __shared__ char dsm[];
    __shared__ int rows[BM];

    int e = blockIdx.z;
    int n_e = g_cnt[e];
    int m0 = blockIdx.y * BM;
    if (m0 >= n_e) return;
    int n0 = blockIdx.x * BN;

    int tid = threadIdx.x;
    int lane = tid & 31;
    int wid = tid >> 5;
    int warp_m = wid >> 2;
    int warp_n = wid & 3;

    if (tid < BM) {
        int m = m0 + tid;
        rows[tid] = (m < n_e) ? g_list[e * BB + m] : -1;
    }
    __syncthreads();

    uint32_t sbase = smem_u32(dsm);
    const __half* Bp = g_w2T + (size_t)(blk * EE + e) * DD * HHv;

    auto load_stage = [&](int chunk, int stage) {
        uint32_t sb = sbase + stage * STAGE_BYT;
        int kofs = chunk * BK;
        #pragma unroll
        for (int j = 0; j < 4; j++) {
            int idx = tid + 256 * j;       // 0..1023
            int row = idx >> 3;
            int seg = idx & 7;
            uint32_t doff = (uint32_t)(row * RSTR + seg * 16);
            int slot = rows[row];
            int sz = (slot >= 0) ? 16 : 0;
            size_t off = (size_t)(slot >= 0 ? slot : 0) * HHv + kofs + seg * 8;
            cp16z(sb + 0 * TILE_BYT + doff, g_Hf + off, sz);
            size_t boff = (size_t)(n0 + row) * HHv + kofs + seg * 8;
            cp16(sb + 1 * TILE_BYT + doff, Bp + boff);
        }
    };

    float acc[4][4][4];
    #pragma unroll
    for (int i = 0; i < 4; i++)
        #pragma unroll
        for (int j = 0; j < 4; j++)
            #pragma unroll
            for (int q = 0; q < 4; q++) acc[i][j][q] = 0.f;

    uint32_t a_row = (uint32_t)(warp_m * 64 + (lane & 15));
    uint32_t a_colp = (uint32_t)((lane >> 4) * 16);
    uint32_t b_row = (uint32_t)(warp_n * 32 + (lane & 7) + ((lane >> 4) & 1) * 8);
    uint32_t b_colp = (uint32_t)(((lane >> 3) & 1) * 16);

    load_stage(0, 0); cp_commit();
    load_stage(1, 1); cp_commit();

    for (int i = 0; i < NCH; i++) {
        if (i + 1 < NCH) asm volatile("cp.async.wait_group 1;" ::: "memory");
        else             asm volatile("cp.async.wait_group 0;" ::: "memory");
        __syncthreads();
        int nx = i + 2;
        if (nx < NCH) { load_stage(nx, nx % NSTAGE); cp_commit(); }

        uint32_t sb = sbase + (i % NSTAGE) * STAGE_BYT;
        uint32_t sA = sb, sB = sb + TILE_BYT;

        #pragma unroll
        for (int kk = 0; kk < BK / 16; kk++) {
            uint32_t kbyte = (uint32_t)(kk * 32);
            uint32_t ah[4][4], bh[2][4];

            #pragma unroll
            for (int mg = 0; mg < 4; mg++)
                ldm4(ah[mg], sA + (a_row + mg * 16) * RSTR + kbyte + a_colp);
            #pragma unroll
            for (int ng = 0; ng < 2; ng++)
                ldm4(bh[ng], sB + (b_row + ng * 16) * RSTR + kbyte + b_colp);

            #pragma unroll
            for (int mg = 0; mg < 4; mg++)
                #pragma unroll
                for (int nf = 0; nf < 4; nf++)
                    mma16816(acc[mg][nf], ah[mg], &bh[nf >> 1][(nf & 1) * 2]);
        }
    }

    int mb = warp_m * 64 + (lane >> 2);
    int nb = n0 + warp_n * 32 + (lane & 3) * 2;
    #pragma unroll
    for (int mg = 0; mg < 4; mg++) {
        int r0 = mb + mg * 16;
        int r1 = r0 + 8;
        int s0 = rows[r0], s1 = rows[r1];
        #pragma unroll
        for (int nf = 0; nf < 4; nf++) {
            int n = nb + nf * 8;
            if (s0 >= 0) {
                __half2 h = __floats2half2_rn(acc[mg][nf][0], acc[mg][nf][1]);
                *(__half2*)(g_Eout + (size_t)s0 * DD + n) = h;
            }
            if (s1 >= 0) {
                __half2 h = __floats2half2_rn(acc[mg][nf][2], acc[mg][nf][3]);
                *(__half2*)(g_Eout + (size_t)s1 * DD + n) = h;
            }
        }
    }
}

// ---------------- layernorm (residual + bias + both slot outputs) ----------------
__device__ __forceinline__ float blockReduceSum(float v, float* red)
{
    __syncthreads();
    int lane = threadIdx.x & 31;
    int w = threadIdx.x >> 5;
    #pragma unroll
    for (int o = 16; o > 0; o >>= 1) v += __shfl_xor_sync(0xffffffffu, v, o);
    if (lane == 0) red[w] = v;
    __syncthreads();
    float r = (lane < 8) ? red[lane] : 0.f;
    #pragma unroll
    for (int o = 4; o > 0; o >>= 1) r += __shfl_xor_sync(0xffffffffu, r, o);
    return r;
}

__global__ __launch_bounds__(256) void k_ln(
    const float* __restrict__ Xext, const float* __restrict__ b2,
    const float* __restrict__ gam, const float* __restrict__ bet,
    float* __restrict__ Yext, int blk)
{
    __shared__ float red[32];
    __shared__ float bc[2];
    int b = blockIdx.x, tid = threadIdx.x;
    float* Y = (blk == 0) ? g_X1 : Yext;
    const float* xrow = ((blk == 0) ? Xext : g_X1) + (size_t)b * DD;

    if (blk == 0 && blockIdx.x == 0 && tid < EE) g_cnt[tid] = 0;  // reset for next block

    int2 se = g_sel[b];
    float2 wv = g_wgt[b];
    const float4* b2a = (const float4*)(b2 + ((size_t)blk * EE + se.x) * DD);
    const float4* b2b = (const float4*)(b2 + ((size_t)blk * EE + se.y) * DD);
    const __half2* e0 = (const __half2*)(g_Eout + (size_t)(2 * b) * DD);
    const __half2* e1 = e0 + DD / 2;

    // each thread handles 4 consecutive elements: n = 4*tid .. 4*tid+3
    float4 xr = ((const float4*)xrow)[tid];
    float4 ba = b2a[tid];
    float4 bb = b2b[tid];
    float2 ea0 = __half22float2(e0[2 * tid]);
    float2 ea1 = __half22float2(e0[2 * tid + 1]);
    float2 eb0 = __half22float2(e1[2 * tid]);
    float2 eb1 = __half22float2(e1[2 * tid + 1]);

    float v[4];
    v[0] = xr.x + wv.x * ba.x + wv.y * bb.x + ea0.x + eb0.x;
    v[1] = xr.y + wv.x * ba.y + wv.y * bb.y + ea0.y + eb0.y;
    v[2] = xr.z + wv.x * ba.z + wv.y * bb.z + ea1.x + eb1.x;
    v[3] = xr.w + wv.x * ba.w + wv.y * bb.w + ea1.y + eb1.y;

    float s = v[0] + v[1] + v[2] + v[3];
    float tot = blockReduceSum(s, red);
    if (tid == 0) bc[0] = tot;
    __syncthreads();
    float mu = bc[0] * (1.f / 1024.f);

    float s2 = 0.f;
    #pragma unroll
    for (int i = 0; i < 4; i++) { float d = v[i] - mu; s2 += d * d; }
    float tot2 = blockReduceSum(s2, red);
    if (tid == 0) bc[1] = tot2;
    __syncthreads();
    float inv = 1.f / sqrtf(bc[1] * (1.f / 1024.f) + 1e-5f);

    float4 gm = ((const float4*)(gam + (size_t)blk * DD))[tid];
    float4 bt = ((const float4*)(bet + (size_t)blk * DD))[tid];
    float4 o;
    o.x = (v[0] - mu) * inv * gm.x + bt.x;
    o.y = (v[1] - mu) * inv * gm.y + bt.y;
    o.z = (v[2] - mu) * inv * gm.z + bt.z;
    o.w = (v[3] - mu) * inv * gm.w + bt.w;
    ((float4*)(Y + (size_t)b * DD))[tid] = o;
}

// ---------------- launch ----------------
extern "C" void kernel_launch(void* const* d_in, const int* in_sizes, int n_in,
                              void* d_out, int out_size)
{
    (void)in_sizes; (void)n_in; (void)out_size;
    const float* x  = (const float*)d_in[0];
    const float* gW = (const float*)d_in[1];
    const float* gb = (const float*)d_in[2];
    const float* qp = (const float*)d_in[3];
    const float* rW = (const float*)d_in[4];
    const float* rb = (const float*)d_in[5];
    const float* w2 = (const float*)d_in[6];
    const float* b2 = (const float*)d_in[7];
    const float* lg = (const float*)d_in[8];
    const float* lb = (const float*)d_in[9];
    float* out = (float*)d_out;

    cudaFuncSetAttribute(k_moe_gemm_mma, cudaFuncAttributeMaxDynamicSharedMemorySize, GEMM_SMEM);

    // one-time per launch: transposes + fp16-convert w2 (+ reset cnt)
    k_gwt<<<(2 * DD * EE + 255) / 256, 256>>>(gW);
    k_w2t<<<dim3(DD / 32, HHv / 32, 2 * EE), 256>>>(w2);

    for (int blk = 0; blk < 2; blk++) {
        k_gate_qsim_w<<<BB / 8, 256>>>(x, gb, qp, blk);
        k_hidden<<<dim3(EE, (2 * BB) / HSLOTS), 256>>>(rW, rb, blk);
        dim3 g2(DD / BN, BB / BM, EE);
        k_moe_gemm_mma<<<g2, 256, GEMM_SMEM>>>(blk);
        k_ln<<<BB, 256>>>(x, b2, lg, lb, out, blk);
    }
}